// round 6
// baseline (speedup 1.0000x reference)
#include <cuda_runtime.h>
#include <cuda_fp16.h>
#include <stdint.h>

// Problem shape: 100000 users + 50000 items, D=64, E=2M.
#define MAXN 150016
#define MAXE 2000000
#define D 64
#define ROW_U2 16              // 64 halfs = 16 uint2 per row
#define SCAN_T 1024
#define MAX_BLOCKS 256
#define NLAYERS 4

// -------- static device scratch --------
__device__ int    g_deg[MAXN];
__device__ float  g_dis[MAXN];
__device__ float  g_inv[MAXN];          // sqrt(deg), 0 if deg==0
__device__ int    g_off[MAXN + 1];
__device__ int    g_cur[MAXN];
__device__ int    g_csr[MAXE];
__device__ int    g_bsum[MAX_BLOCKS];   // published block aggregates
__device__ int    g_flag[MAX_BLOCKS];   // publication flags
// t_0..t_4 message buffers, fp16: t_k = dis * e_k
__device__ __half g_t[(size_t)(NLAYERS + 1) * MAXN * D];

// -------- kernels --------

// Counts in-degree; blocks 0..MAX_BLOCKS-1 also reset the lookback flags
// (visible to the scan kernel via stream ordering).
__global__ void count_deg_kernel(const int* __restrict__ dst, int E, int N) {
    if (threadIdx.x == 0 && blockIdx.x < MAX_BLOCKS) g_flag[blockIdx.x] = 0;
    int e = blockIdx.x * blockDim.x + threadIdx.x;
    if (e < E) {
        int d = dst[e];
        if ((unsigned)d < (unsigned)N) atomicAdd(&g_deg[d], 1);
    }
}

// Single-pass scan + finalize + t0 init.
// Block b scans deg[b*1024 .. b*1024+1023], publishes its aggregate, does a
// warp-parallel lookback over predecessors, then writes off/cur/dis/inv and
// the t0 rows for its node chunk.
__global__ void __launch_bounds__(SCAN_T)
scan_fused_kernel(const float* __restrict__ emb_users,
                  const float* __restrict__ emb_items,
                  int nu_elems, int N) {
    __shared__ int wsum[32];
    __shared__ int block_prefix_s;
    int t = threadIdx.x;
    int b = blockIdx.x;
    int i = b * SCAN_T + t;
    int v = (i < N) ? g_deg[i] : 0;

    // warp inclusive scan
    int x = v;
    #pragma unroll
    for (int off = 1; off < 32; off <<= 1) {
        int y = __shfl_up_sync(0xffffffff, x, off);
        if ((t & 31) >= off) x += y;
    }
    if ((t & 31) == 31) wsum[t >> 5] = x;
    __syncthreads();

    if (t < 32) {
        int w = wsum[t];
        #pragma unroll
        for (int off = 1; off < 32; off <<= 1) {
            int y = __shfl_up_sync(0xffffffff, w, off);
            if (t >= off) w += y;
        }
        wsum[t] = w;
    }
    __syncthreads();

    int base = (t >= 32) ? wsum[(t >> 5) - 1] : 0;
    int incl_local = base + x;                 // inclusive within block
    int block_total = wsum[31];

    // publish aggregate, then warp-0 lookback
    if (t == 0) {
        g_bsum[b] = block_total;
        __threadfence();
        atomicExch(&g_flag[b], 1);
    }
    if (t < 32) {
        int acc = 0;
        for (int pb = t; pb < b; pb += 32) {
            while (atomicAdd(&g_flag[pb], 0) == 0) { }
            acc += atomicAdd(&g_bsum[pb], 0);
        }
        #pragma unroll
        for (int off = 16; off > 0; off >>= 1)
            acc += __shfl_down_sync(0xffffffff, acc, off);
        if (t == 0) block_prefix_s = acc;
    }
    __syncthreads();
    int bp = block_prefix_s;

    float disv = 0.0f;
    if (i < N) {
        int incl = bp + incl_local;
        g_off[i + 1] = incl;
        g_cur[i]     = incl - v;
        float fd = (float)v;
        disv = (v > 0) ? rsqrtf(fd) : 0.0f;
        g_dis[i] = disv;
        g_inv[i] = (v > 0) ? sqrtf(fd) : 0.0f;
        if (i == 0) g_off[0] = 0;
    }
    __syncthreads();

    // t0 init for this block's node chunk: elements [b*1024*64, ...) flat.
    int chunk_nodes = min(SCAN_T, N - b * SCAN_T);
    if (chunk_nodes <= 0) return;
    int elems = chunk_nodes * D;
    size_t ebase = (size_t)b * SCAN_T * D;
    for (int k = t; k < elems; k += SCAN_T) {
        size_t idx = ebase + k;
        float v0 = (idx < (size_t)nu_elems) ? emb_users[idx]
                                            : emb_items[idx - nu_elems];
        g_t[idx] = __float2half(g_dis[idx >> 6] * v0);
    }
}

__global__ void scatter_kernel(const int* __restrict__ src,
                               const int* __restrict__ dst, int E, int N) {
    int e = blockIdx.x * blockDim.x + threadIdx.x;
    if (e < E) {
        int d = dst[e];
        int s = src[e];
        if ((unsigned)d < (unsigned)N && (unsigned)s < (unsigned)N) {
            int pos = atomicAdd(&g_cur[d], 1);
            if ((unsigned)pos < (unsigned)MAXE) g_csr[pos] = s;
        }
    }
}

// One layer: reads t_{k-1}, writes t_k. Two nodes per warp (16 lanes each),
// each lane gathers 8B (uint2 = 4 halfs).
__global__ void __launch_bounds__(256)
layer_kernel(int N, int kin) {
    int gtid = blockIdx.x * blockDim.x + threadIdx.x;
    int w    = gtid >> 5;
    int lane = gtid & 31;
    int node = (w << 1) | (lane >> 4);
    int sub  = lane & 15;
    if (node >= N) return;

    const uint2* __restrict__ tin  =
        (const uint2*)(g_t + (size_t)kin * MAXN * D);
    uint2* __restrict__ tout =
        (uint2*)(g_t + (size_t)(kin + 1) * MAXN * D);

    int s = g_off[node];
    int e = g_off[node + 1];

    float ax = 0.f, ay = 0.f, az = 0.f, aw = 0.f;
    int p = s;
    for (; p + 3 < e; p += 4) {
        int u0 = g_csr[p];
        int u1 = g_csr[p + 1];
        int u2 = g_csr[p + 2];
        int u3 = g_csr[p + 3];
        uint2 r0 = __ldg(&tin[(size_t)u0 * ROW_U2 + sub]);
        uint2 r1 = __ldg(&tin[(size_t)u1 * ROW_U2 + sub]);
        uint2 r2 = __ldg(&tin[(size_t)u2 * ROW_U2 + sub]);
        uint2 r3 = __ldg(&tin[(size_t)u3 * ROW_U2 + sub]);
        float2 a0 = __half22float2(*(__half2*)&r0.x);
        float2 b0 = __half22float2(*(__half2*)&r0.y);
        float2 a1 = __half22float2(*(__half2*)&r1.x);
        float2 b1 = __half22float2(*(__half2*)&r1.y);
        float2 a2 = __half22float2(*(__half2*)&r2.x);
        float2 b2 = __half22float2(*(__half2*)&r2.y);
        float2 a3 = __half22float2(*(__half2*)&r3.x);
        float2 b3 = __half22float2(*(__half2*)&r3.y);
        ax += a0.x + a1.x + a2.x + a3.x;
        ay += a0.y + a1.y + a2.y + a3.y;
        az += b0.x + b1.x + b2.x + b3.x;
        aw += b0.y + b1.y + b2.y + b3.y;
    }
    for (; p < e; p++) {
        int u0 = g_csr[p];
        uint2 r0 = __ldg(&tin[(size_t)u0 * ROW_U2 + sub]);
        float2 a0 = __half22float2(*(__half2*)&r0.x);
        float2 b0 = __half22float2(*(__half2*)&r0.y);
        ax += a0.x; ay += a0.y; az += b0.x; aw += b0.y;
    }

    float dv = g_dis[node];
    float d2 = dv * dv;          // t_next = dis^2 * sum
    uint2 o;
    __half2 lo = __floats2half2_rn(d2 * ax, d2 * ay);
    __half2 hi = __floats2half2_rn(d2 * az, d2 * aw);
    o.x = *(uint32_t*)&lo;
    o.y = *(uint32_t*)&hi;
    tout[(size_t)node * ROW_U2 + sub] = o;
}

// out = (emb0 + sqrt(deg) * (t1+t2+t3+t4)) / 25.
__global__ void final_kernel(const float* __restrict__ emb_users,
                             const float* __restrict__ emb_items,
                             float* __restrict__ out,
                             int nu_pairs, int total_pairs) {
    int idx = blockIdx.x * blockDim.x + threadIdx.x;   // half2 index
    if (idx >= total_pairs) return;
    int node = idx >> 5;

    const __half2* t1 = (const __half2*)(g_t + (size_t)1 * MAXN * D);
    const __half2* t2 = (const __half2*)(g_t + (size_t)2 * MAXN * D);
    const __half2* t3 = (const __half2*)(g_t + (size_t)3 * MAXN * D);
    const __half2* t4 = (const __half2*)(g_t + (size_t)4 * MAXN * D);

    float2 s1 = __half22float2(t1[idx]);
    float2 s2 = __half22float2(t2[idx]);
    float2 s3 = __half22float2(t3[idx]);
    float2 s4 = __half22float2(t4[idx]);

    const float2* embu = (const float2*)emb_users;
    const float2* embi = (const float2*)emb_items;
    float2 e0 = (idx < nu_pairs) ? embu[idx] : embi[idx - nu_pairs];

    float inv = g_inv[node];
    const float sc = 1.0f / 25.0f;
    float2 r;
    r.x = (e0.x + inv * (s1.x + s2.x + s3.x + s4.x)) * sc;
    r.y = (e0.y + inv * (s1.y + s2.y + s3.y + s4.y)) * sc;
    ((float2*)out)[idx] = r;
}

// -------- launch --------
extern "C" void kernel_launch(void* const* d_in, const int* in_sizes, int n_in,
                              void* d_out, int out_size) {
    const float* emb_users = (const float*)d_in[0];
    const float* emb_items = (const float*)d_in[1];
    const int*   edge      = (const int*)d_in[2];   // int32

    int nu_elems = in_sizes[0];
    int ni_elems = in_sizes[1];
    int E        = in_sizes[2] / 2;
    int NU = nu_elems / D;
    int NI = ni_elems / D;
    int N  = NU + NI;

    const int* src = edge;
    const int* dst = edge + E;
    float* out = (float*)d_out;

    const int T = 256;
    int nScanBlocks = (N + SCAN_T - 1) / SCAN_T;   // 147 <= 148 SMs (lookback safe)

    // zero g_deg via memset node (not a kernel launch)
    void* deg_ptr = nullptr;
    cudaGetSymbolAddress(&deg_ptr, g_deg);
    cudaMemsetAsync(deg_ptr, 0, (size_t)N * sizeof(int));

    count_deg_kernel<<<(E + T - 1) / T, T>>>(dst, E, N);
    scan_fused_kernel<<<nScanBlocks, SCAN_T>>>(emb_users, emb_items, nu_elems, N);
    scatter_kernel<<<(E + T - 1) / T, T>>>(src, dst, E, N);

    int layer_blocks = (N * 16 + T - 1) / T;   // 2 nodes per warp
    layer_kernel<<<layer_blocks, T>>>(N, 0);
    layer_kernel<<<layer_blocks, T>>>(N, 1);
    layer_kernel<<<layer_blocks, T>>>(N, 2);
    layer_kernel<<<layer_blocks, T>>>(N, 3);

    int total_pairs = N * (D / 2);
    final_kernel<<<(total_pairs + T - 1) / T, T>>>(emb_users, emb_items, out,
                                                   nu_elems / 2, total_pairs);
}

// round 7
// speedup vs baseline: 1.0365x; 1.0365x over previous
#include <cuda_runtime.h>
#include <cuda_fp16.h>
#include <stdint.h>

// Problem shape: 100000 users + 50000 items, D=64, E=2M.
#define MAXN 150016
#define MAXE 2000000
#define D 64
#define ROW_U2 16              // 64 halfs = 16 uint2 per row
#define SCAN_T 1024
#define MAX_BLOCKS 256
#define NLAYERS 4

// -------- static device scratch --------
__device__ int    g_deg[MAXN];
__device__ float  g_dis[MAXN];
__device__ float  g_inv[MAXN];          // sqrt(deg), 0 if deg==0
__device__ int    g_off[MAXN + 1];
__device__ int    g_cur[MAXN];
__device__ int    g_csr[MAXE];
__device__ int    g_bsum[MAX_BLOCKS];   // published block aggregates
__device__ int    g_flag[MAX_BLOCKS];   // publication flags
// t_0..t_4 message buffers, fp16: t_k = dis * e_k
__device__ __half g_t[(size_t)(NLAYERS + 1) * MAXN * D];

// -------- kernels --------

__global__ void count_deg_kernel(const int* __restrict__ dst, int E, int N) {
    if (threadIdx.x == 0 && blockIdx.x < MAX_BLOCKS) g_flag[blockIdx.x] = 0;
    int e = blockIdx.x * blockDim.x + threadIdx.x;
    if (e < E) {
        int d = dst[e];
        if ((unsigned)d < (unsigned)N) atomicAdd(&g_deg[d], 1);
    }
}

// Single-pass scan (decoupled lookback) + finalize + t0 init.
__global__ void __launch_bounds__(SCAN_T)
scan_fused_kernel(const float* __restrict__ emb_users,
                  const float* __restrict__ emb_items,
                  int nu_elems, int N) {
    __shared__ int wsum[32];
    __shared__ int block_prefix_s;
    int t = threadIdx.x;
    int b = blockIdx.x;
    int i = b * SCAN_T + t;
    int v = (i < N) ? g_deg[i] : 0;

    int x = v;
    #pragma unroll
    for (int off = 1; off < 32; off <<= 1) {
        int y = __shfl_up_sync(0xffffffff, x, off);
        if ((t & 31) >= off) x += y;
    }
    if ((t & 31) == 31) wsum[t >> 5] = x;
    __syncthreads();

    if (t < 32) {
        int w = wsum[t];
        #pragma unroll
        for (int off = 1; off < 32; off <<= 1) {
            int y = __shfl_up_sync(0xffffffff, w, off);
            if (t >= off) w += y;
        }
        wsum[t] = w;
    }
    __syncthreads();

    int base = (t >= 32) ? wsum[(t >> 5) - 1] : 0;
    int incl_local = base + x;
    int block_total = wsum[31];

    if (t == 0) {
        g_bsum[b] = block_total;
        __threadfence();
        atomicExch(&g_flag[b], 1);
    }
    if (t < 32) {
        int acc = 0;
        for (int pb = t; pb < b; pb += 32) {
            while (atomicAdd(&g_flag[pb], 0) == 0) { }
            acc += atomicAdd(&g_bsum[pb], 0);
        }
        #pragma unroll
        for (int off = 16; off > 0; off >>= 1)
            acc += __shfl_down_sync(0xffffffff, acc, off);
        if (t == 0) block_prefix_s = acc;
    }
    __syncthreads();
    int bp = block_prefix_s;

    if (i < N) {
        int incl = bp + incl_local;
        g_off[i + 1] = incl;
        g_cur[i]     = incl - v;
        float fd = (float)v;
        g_dis[i] = (v > 0) ? rsqrtf(fd) : 0.0f;
        g_inv[i] = (v > 0) ? sqrtf(fd) : 0.0f;
        if (i == 0) g_off[0] = 0;
    }
    __syncthreads();

    int chunk_nodes = min(SCAN_T, N - b * SCAN_T);
    if (chunk_nodes <= 0) return;
    int elems = chunk_nodes * D;
    size_t ebase = (size_t)b * SCAN_T * D;
    for (int k = t; k < elems; k += SCAN_T) {
        size_t idx = ebase + k;
        float v0 = (idx < (size_t)nu_elems) ? emb_users[idx]
                                            : emb_items[idx - nu_elems];
        g_t[idx] = __float2half(g_dis[idx >> 6] * v0);
    }
}

__global__ void scatter_kernel(const int* __restrict__ src,
                               const int* __restrict__ dst, int E, int N) {
    int e = blockIdx.x * blockDim.x + threadIdx.x;
    if (e < E) {
        int d = dst[e];
        int s = src[e];
        if ((unsigned)d < (unsigned)N && (unsigned)s < (unsigned)N) {
            int pos = atomicAdd(&g_cur[d], 1);
            if ((unsigned)pos < (unsigned)MAXE) g_csr[pos] = s;
        }
    }
}

// One layer: reads t_{k-1}, writes t_k. Two nodes per warp (16 lanes each),
// each lane gathers 8B (uint2 = 4 halfs). csr indices fetched as int4;
// 4-edge groups pairwise-summed in fp16 then folded to fp32 once per group.
__global__ void __launch_bounds__(256)
layer_kernel(int N, int kin) {
    int gtid = blockIdx.x * blockDim.x + threadIdx.x;
    int w    = gtid >> 5;
    int lane = gtid & 31;
    int node = (w << 1) | (lane >> 4);
    int sub  = lane & 15;
    if (node >= N) return;

    const uint2* __restrict__ tin  =
        (const uint2*)(g_t + (size_t)kin * MAXN * D);
    uint2* __restrict__ tout =
        (uint2*)(g_t + (size_t)(kin + 1) * MAXN * D);

    int s = g_off[node];
    int e = g_off[node + 1];

    float ax = 0.f, ay = 0.f, az = 0.f, aw = 0.f;
    int p = s;

    // head: align p to 4 for int4 loads (fp32 accumulate)
    for (; p < e && (p & 3); p++) {
        int u0 = g_csr[p];
        uint2 r0 = __ldg(&tin[(size_t)u0 * ROW_U2 + sub]);
        float2 a0 = __half22float2(*(__half2*)&r0.x);
        float2 b0 = __half22float2(*(__half2*)&r0.y);
        ax += a0.x; ay += a0.y; az += b0.x; aw += b0.y;
    }

    // main: 4 edges per iteration
    for (; p + 3 < e; p += 4) {
        int4 u = *(const int4*)&g_csr[p];      // LDG.128
        uint2 r0 = __ldg(&tin[(size_t)u.x * ROW_U2 + sub]);
        uint2 r1 = __ldg(&tin[(size_t)u.y * ROW_U2 + sub]);
        uint2 r2 = __ldg(&tin[(size_t)u.z * ROW_U2 + sub]);
        uint2 r3 = __ldg(&tin[(size_t)u.w * ROW_U2 + sub]);
        // pairwise fp16 tree (6 HADD2)
        __half2 lo01 = __hadd2(*(__half2*)&r0.x, *(__half2*)&r1.x);
        __half2 lo23 = __hadd2(*(__half2*)&r2.x, *(__half2*)&r3.x);
        __half2 hi01 = __hadd2(*(__half2*)&r0.y, *(__half2*)&r1.y);
        __half2 hi23 = __hadd2(*(__half2*)&r2.y, *(__half2*)&r3.y);
        __half2 lo = __hadd2(lo01, lo23);
        __half2 hi = __hadd2(hi01, hi23);
        float2 fl = __half22float2(lo);
        float2 fh = __half22float2(hi);
        ax += fl.x; ay += fl.y; az += fh.x; aw += fh.y;
    }

    // tail
    for (; p < e; p++) {
        int u0 = g_csr[p];
        uint2 r0 = __ldg(&tin[(size_t)u0 * ROW_U2 + sub]);
        float2 a0 = __half22float2(*(__half2*)&r0.x);
        float2 b0 = __half22float2(*(__half2*)&r0.y);
        ax += a0.x; ay += a0.y; az += b0.x; aw += b0.y;
    }

    float dv = g_dis[node];
    float d2 = dv * dv;          // t_next = dis^2 * sum
    uint2 o;
    __half2 lo = __floats2half2_rn(d2 * ax, d2 * ay);
    __half2 hi = __floats2half2_rn(d2 * az, d2 * aw);
    o.x = *(uint32_t*)&lo;
    o.y = *(uint32_t*)&hi;
    tout[(size_t)node * ROW_U2 + sub] = o;
}

// out = (emb0 + sqrt(deg) * (t1+t2+t3+t4)) / 25.
__global__ void final_kernel(const float* __restrict__ emb_users,
                             const float* __restrict__ emb_items,
                             float* __restrict__ out,
                             int nu_pairs, int total_pairs) {
    int idx = blockIdx.x * blockDim.x + threadIdx.x;   // half2 index
    if (idx >= total_pairs) return;
    int node = idx >> 5;

    const __half2* t1 = (const __half2*)(g_t + (size_t)1 * MAXN * D);
    const __half2* t2 = (const __half2*)(g_t + (size_t)2 * MAXN * D);
    const __half2* t3 = (const __half2*)(g_t + (size_t)3 * MAXN * D);
    const __half2* t4 = (const __half2*)(g_t + (size_t)4 * MAXN * D);

    float2 s1 = __half22float2(t1[idx]);
    float2 s2 = __half22float2(t2[idx]);
    float2 s3 = __half22float2(t3[idx]);
    float2 s4 = __half22float2(t4[idx]);

    const float2* embu = (const float2*)emb_users;
    const float2* embi = (const float2*)emb_items;
    float2 e0 = (idx < nu_pairs) ? embu[idx] : embi[idx - nu_pairs];

    float inv = g_inv[node];
    const float sc = 1.0f / 25.0f;
    float2 r;
    r.x = (e0.x + inv * (s1.x + s2.x + s3.x + s4.x)) * sc;
    r.y = (e0.y + inv * (s1.y + s2.y + s3.y + s4.y)) * sc;
    ((float2*)out)[idx] = r;
}

// -------- launch --------
extern "C" void kernel_launch(void* const* d_in, const int* in_sizes, int n_in,
                              void* d_out, int out_size) {
    const float* emb_users = (const float*)d_in[0];
    const float* emb_items = (const float*)d_in[1];
    const int*   edge      = (const int*)d_in[2];   // int32

    int nu_elems = in_sizes[0];
    int ni_elems = in_sizes[1];
    int E        = in_sizes[2] / 2;
    int NU = nu_elems / D;
    int NI = ni_elems / D;
    int N  = NU + NI;

    const int* src = edge;
    const int* dst = edge + E;
    float* out = (float*)d_out;

    const int T = 256;
    int nScanBlocks = (N + SCAN_T - 1) / SCAN_T;   // 147 <= 148 SMs

    void* deg_ptr = nullptr;
    cudaGetSymbolAddress(&deg_ptr, g_deg);
    cudaMemsetAsync(deg_ptr, 0, (size_t)N * sizeof(int));

    count_deg_kernel<<<(E + T - 1) / T, T>>>(dst, E, N);
    scan_fused_kernel<<<nScanBlocks, SCAN_T>>>(emb_users, emb_items, nu_elems, N);
    scatter_kernel<<<(E + T - 1) / T, T>>>(src, dst, E, N);

    int layer_blocks = (N * 16 + T - 1) / T;   // 2 nodes per warp
    layer_kernel<<<layer_blocks, T>>>(N, 0);
    layer_kernel<<<layer_blocks, T>>>(N, 1);
    layer_kernel<<<layer_blocks, T>>>(N, 2);
    layer_kernel<<<layer_blocks, T>>>(N, 3);

    int total_pairs = N * (D / 2);
    final_kernel<<<(total_pairs + T - 1) / T, T>>>(emb_users, emb_items, out,
                                                   nu_elems / 2, total_pairs);
}